// round 10
// baseline (speedup 1.0000x reference)
#include <cuda_runtime.h>
#include <math.h>

#define BN 16384
#define NCS 64
#define NFS 128
#define NTOT 192
#define H 64
#define PT 64          // points per block
#define PAIRS 32
#define MT 256

typedef unsigned long long u64;

// ---------------- scratch ----------------
__device__ float4 g_rgbd_c[BN * NCS];
__device__ float4 g_rgbd_f[BN * NTOT];
__device__ float  g_zt[NTOT * BN];       // fine z_vals transposed: z[j*BN + b]

__device__ __forceinline__ float tval_of(float nb, float fb, int i) {
    float tt = (float)i * (1.0f / 63.0f);
    return nb * (1.0f - tt) + fb * tt;
}

// ---- f32x2 packed helpers ----
__device__ __forceinline__ u64 pk2(float lo, float hi) {
    u64 r; asm("mov.b64 %0, {%1, %2};" : "=l"(r) : "f"(lo), "f"(hi)); return r;
}
__device__ __forceinline__ void upk2(u64 v, float& lo, float& hi) {
    asm("mov.b64 {%0, %1}, %2;" : "=f"(lo), "=f"(hi) : "l"(v));
}
__device__ __forceinline__ u64 ffma2(u64 a, u64 b, u64 c) {
    u64 d; asm("fma.rn.f32x2 %0, %1, %2, %3;" : "=l"(d) : "l"(a), "l"(b), "l"(c)); return d;
}
__device__ __forceinline__ u64 relu2(u64 v) {
    float a, b; upk2(v, a, b);
    return pk2(fmaxf(a, 0.0f), fmaxf(b, 0.0f));
}

// ------------- MLP: 64 points/block (32 pairs), 256 threads -------------
// Thread = (pair, jg): pair of points packed in f32x2 lanes, jg owns 8 hidden
// units (4 unit-pairs). Swap trick gives all 4 point x unit combos from natural
// (non-duplicated) packed operands: accA = h*w, accB = swap(h)*w.
__global__ __launch_bounds__(MT) void mlp_pair_kernel(
    const float* __restrict__ origins, const float* __restrict__ dirs,
    const float* __restrict__ nearp,   const float* __restrict__ farp,
    const float* __restrict__ w1, const float* __restrict__ b1,
    const float* __restrict__ w2, const float* __restrict__ b2,
    const float* __restrict__ wr, const float* __restrict__ br,
    const float* __restrict__ wd, const float* __restrict__ bd,
    int use_z, float4* __restrict__ out_rgbd)
{
    __shared__ __align__(16) u64 s_h1[H * 34];      // [k*34 + pair]  (pad 34 for banks)
    __shared__ __align__(16) u64 s_w2p[H * 8 * 6];  // [(k*8+jg)*6 + i], i<4: (w2[k][2jp],w2[k][2jp+1])
    __shared__ __align__(16) u64 s_w1d[4 * H];      // dup rows: x,y,z,b1
    __shared__ __align__(16) u64 s_b2p[PAIRS];      // (b2[2jp], b2[2jp+1])
    __shared__ float4 s_hd4[H];                     // (wr0,wr1,wr2,wd) per unit
    __shared__ float  s_hb[4];

    int tid = threadIdx.x;

    // ---- stage weights ----
    for (int i = tid; i < H * 32; i += MT) {        // 2048 w2 pairs
        int k = i >> 5, jp = i & 31;
        int jg = jp >> 2, ii = jp & 3;
        s_w2p[(k * 8 + jg) * 6 + ii] = pk2(w2[k * H + 2 * jp], w2[k * H + 2 * jp + 1]);
    }
    if (tid < H) {
        s_w1d[tid]           = pk2(w1[tid],         w1[tid]);
        s_w1d[H + tid]       = pk2(w1[H + tid],     w1[H + tid]);
        s_w1d[2 * H + tid]   = pk2(w1[2 * H + tid], w1[2 * H + tid]);
        s_w1d[3 * H + tid]   = pk2(b1[tid],         b1[tid]);
        s_hd4[tid] = make_float4(wr[tid * 3], wr[tid * 3 + 1], wr[tid * 3 + 2], wd[tid]);
    }
    if (tid < PAIRS) s_b2p[tid] = pk2(b2[2 * tid], b2[2 * tid + 1]);
    if (tid < 3) s_hb[tid] = br[tid];
    if (tid == 3) s_hb[3] = bd[0];
    __syncthreads();

    unsigned base = blockIdx.x * PT;
    int pair = tid >> 3;        // 0..31
    int jg   = tid & 7;         // 0..7

    unsigned pf0 = base + pair;
    unsigned pf1 = pf0 + PAIRS;

    // ---- phase 1: layer-1 -> SMEM (thread covers its pair, k = jg + 8*kk) ----
    {
        int b0 = (int)(pf0 & (BN - 1)), j0 = (int)(pf0 >> 14);
        int b1i = (int)(pf1 & (BN - 1)), j1 = (int)(pf1 >> 14);
        float t0 = use_z ? g_zt[pf0] : tval_of(nearp[b0], farp[b0], j0);
        float t1 = use_z ? g_zt[pf1] : tval_of(nearp[b1i], farp[b1i], j1);
        float x0 = origins[3 * b0]     + t0 * dirs[3 * b0];
        float y0 = origins[3 * b0 + 1] + t0 * dirs[3 * b0 + 1];
        float z0 = origins[3 * b0 + 2] + t0 * dirs[3 * b0 + 2];
        float x1 = origins[3 * b1i]     + t1 * dirs[3 * b1i];
        float y1 = origins[3 * b1i + 1] + t1 * dirs[3 * b1i + 1];
        float z1 = origins[3 * b1i + 2] + t1 * dirs[3 * b1i + 2];
        u64 xp = pk2(x0, x1), yp = pk2(y0, y1), zp = pk2(z0, z1);
        #pragma unroll
        for (int kk = 0; kk < 8; kk++) {
            int k = jg + 8 * kk;     // interleaved k to spread store banks
            u64 v = ffma2(xp, s_w1d[k], s_w1d[3 * H + k]);
            v = ffma2(yp, s_w1d[H + k], v);
            v = ffma2(zp, s_w1d[2 * H + k], v);
            s_h1[k * 34 + pair] = relu2(v);
        }
    }
    __syncthreads();

    // ---- phase 2: layer-2, 8 FFMA2 per k, 8 independent chains ----
    u64 accA[4], accB[4];
    #pragma unroll
    for (int i = 0; i < 4; i++) {
        u64 bb = s_b2p[jg * 4 + i];
        accA[i] = bb; accB[i] = bb;
    }
    #pragma unroll 2
    for (int k = 0; k < H; k++) {
        u64 h = s_h1[k * 34 + pair];
        float ha, hb; upk2(h, ha, hb);
        u64 hs = pk2(hb, ha);
        const u64* wrow = &s_w2p[(k * 8 + jg) * 6];
        ulonglong2 wv0 = *reinterpret_cast<const ulonglong2*>(wrow);
        ulonglong2 wv1 = *reinterpret_cast<const ulonglong2*>(wrow + 2);
        accA[0] = ffma2(h,  wv0.x, accA[0]);
        accB[0] = ffma2(hs, wv0.x, accB[0]);
        accA[1] = ffma2(h,  wv0.y, accA[1]);
        accB[1] = ffma2(hs, wv0.y, accB[1]);
        accA[2] = ffma2(h,  wv1.x, accA[2]);
        accB[2] = ffma2(hs, wv1.x, accB[2]);
        accA[3] = ffma2(h,  wv1.y, accA[3]);
        accB[3] = ffma2(hs, wv1.y, accB[3]);
    }

    // ---- phase 3: relu + head partials + 8-lane reduce ----
    float pA0 = 0.f, pA1 = 0.f, pA2 = 0.f, pA3 = 0.f;
    float pB0 = 0.f, pB1 = 0.f, pB2 = 0.f, pB3 = 0.f;
    #pragma unroll
    for (int i = 0; i < 4; i++) {
        int jp = jg * 4 + i;
        float a0, b1v, b0v, a1;
        upk2(accA[i], a0, b1v);   // (pA,j0), (pB,j1)
        upk2(accB[i], b0v, a1);   // (pB,j0), (pA,j1)
        a0  = fmaxf(a0, 0.f);  a1  = fmaxf(a1, 0.f);
        b0v = fmaxf(b0v, 0.f); b1v = fmaxf(b1v, 0.f);
        float4 d0 = s_hd4[2 * jp];
        float4 d1 = s_hd4[2 * jp + 1];
        pA0 += a0 * d0.x + a1 * d1.x;
        pA1 += a0 * d0.y + a1 * d1.y;
        pA2 += a0 * d0.z + a1 * d1.z;
        pA3 += a0 * d0.w + a1 * d1.w;
        pB0 += b0v * d0.x + b1v * d1.x;
        pB1 += b0v * d0.y + b1v * d1.y;
        pB2 += b0v * d0.z + b1v * d1.z;
        pB3 += b0v * d0.w + b1v * d1.w;
    }
    #pragma unroll
    for (int o = 1; o < 8; o <<= 1) {
        pA0 += __shfl_xor_sync(0xffffffffu, pA0, o);
        pA1 += __shfl_xor_sync(0xffffffffu, pA1, o);
        pA2 += __shfl_xor_sync(0xffffffffu, pA2, o);
        pA3 += __shfl_xor_sync(0xffffffffu, pA3, o);
        pB0 += __shfl_xor_sync(0xffffffffu, pB0, o);
        pB1 += __shfl_xor_sync(0xffffffffu, pB1, o);
        pB2 += __shfl_xor_sync(0xffffffffu, pB2, o);
        pB3 += __shfl_xor_sync(0xffffffffu, pB3, o);
    }
    if (jg == 0) {
        float4 oA, oB;
        oA.x = 1.f / (1.f + expf(-(pA0 + s_hb[0])));
        oA.y = 1.f / (1.f + expf(-(pA1 + s_hb[1])));
        oA.z = 1.f / (1.f + expf(-(pA2 + s_hb[2])));
        oA.w = fmaxf(pA3 + s_hb[3], 0.f);
        oB.x = 1.f / (1.f + expf(-(pB0 + s_hb[0])));
        oB.y = 1.f / (1.f + expf(-(pB1 + s_hb[1])));
        oB.z = 1.f / (1.f + expf(-(pB2 + s_hb[2])));
        oB.w = fmaxf(pB3 + s_hb[3], 0.f);
        out_rgbd[pf0] = oA;
        out_rgbd[pf1] = oB;
    }
}

// ---------------- coarse render + inverse-CDF + merge : one thread per ray (verified) ----------------
__global__ __launch_bounds__(128) void render_coarse_kernel(
    const float* __restrict__ origins, const float* __restrict__ dirs,
    const float* __restrict__ nearp,   const float* __restrict__ farp,
    const float* __restrict__ bkgd,
    float* __restrict__ out)
{
    int b = blockIdx.x * blockDim.x + threadIdx.x;
    if (b >= BN) return;

    float nb = nearp[b], fb = farp[b];
    float n0 = nearp[0], f0 = farp[0];
    float dx = dirs[3 * b], dy = dirs[3 * b + 1], dz = dirs[3 * b + 2];
    float dn = sqrtf(dx * dx + dy * dy + dz * dz);

    float w[NCS];
    float T = 0.f, c0 = 0.f, c1 = 0.f, c2 = 0.f, acc = 0.f, depth = 0.f, s0 = 0.f;
    for (int j = 0; j < NCS; j++) {
        float tj  = tval_of(nb, fb, j);
        float tdist = (j < NCS - 1) ? (tval_of(nb, fb, j + 1) - tj) : 1e10f;
        float4 rd = g_rgbd_c[j * BN + b];
        float dd = rd.w * tdist * dn;
        float alpha = 1.0f - expf(-dd);
        float trans = expf(-T);
        float wj = alpha * trans;
        T += dd;
        w[j] = wj;
        c0 += wj * rd.x; c1 += wj * rd.y; c2 += wj * rd.z;
        acc += wj;
        depth += wj * tj;
        s0 += wj * tval_of(n0, f0, j);
    }
    c0 += bkgd[0] * (1.0f - acc);
    c1 += bkgd[1] * (1.0f - acc);
    c2 += bkgd[2] * (1.0f - acc);

    float o0x = origins[0], o0y = origins[1], o0z = origins[2];
    float d0x = dirs[0],    d0y = dirs[1],    d0z = dirs[2];
    float* po = out + (size_t)b * 16;
    po[0] = c0; po[1] = c1; po[2] = c2;
    po[3] = depth; po[4] = acc;
    po[5] = acc * o0x + s0 * d0x;
    po[6] = acc * o0y + s0 * d0y;
    po[7] = acc * o0z + s0 * d0z;

    // ---- piecewise-constant PDF inverse-CDF sampling ----
    float ws = 0.f;
    for (int i = 0; i < 62; i++) ws += w[i + 1];
    float pad  = fmaxf(1e-5f - ws, 0.f);
    float padd = pad * (1.0f / 62.0f);
    ws += pad;
    float inv_ws = 1.0f / ws;

    float cdf[63];
    cdf[0] = 0.f;
    float run = 0.f;
    for (int i = 1; i <= 61; i++) {
        run += (w[i] + padd) * inv_ws;
        cdf[i] = fminf(run, 1.f);
    }
    cdf[62] = 1.f;

    const float F32EPS = 1.1920928955078125e-7f;
    const float ustep = (1.0f - F32EPS) * (1.0f / 127.0f);
    int i0 = 0;
    int ti = 0;
    int outn = 0;
    for (int s = 0; s < NFS; s++) {
        float u = (float)s * ustep;
        while (i0 + 1 < 62 + 1 && cdf[i0 + 1] <= u) i0++;
        float cg0 = cdf[i0], cg1 = cdf[i0 + 1];
        float bg0 = 0.5f * (tval_of(nb, fb, i0)     + tval_of(nb, fb, i0 + 1));
        float bg1 = 0.5f * (tval_of(nb, fb, i0 + 1) + tval_of(nb, fb, i0 + 2));
        float denom = cg1 - cg0;
        float tf = (denom > 0.f) ? (u - cg0) / denom : 0.f;
        tf = fminf(fmaxf(tf, 0.f), 1.f);
        float zs = bg0 + tf * (bg1 - bg0);
        while (ti < NCS && tval_of(nb, fb, ti) <= zs) {
            g_zt[outn * BN + b] = tval_of(nb, fb, ti);
            outn++; ti++;
        }
        g_zt[outn * BN + b] = zs;
        outn++;
    }
    while (ti < NCS) {
        g_zt[outn * BN + b] = tval_of(nb, fb, ti);
        outn++; ti++;
    }
}

// ---------------- fine render : one thread per ray (verified) ----------------
__global__ __launch_bounds__(128) void render_fine_kernel(
    const float* __restrict__ origins, const float* __restrict__ dirs,
    const float* __restrict__ bkgd,
    float* __restrict__ out)
{
    int b = blockIdx.x * blockDim.x + threadIdx.x;
    if (b >= BN) return;

    float dx = dirs[3 * b], dy = dirs[3 * b + 1], dz = dirs[3 * b + 2];
    float dn = sqrtf(dx * dx + dy * dy + dz * dz);

    float T = 0.f, c0 = 0.f, c1 = 0.f, c2 = 0.f, acc = 0.f, depth = 0.f, s1 = 0.f;
    float zj = g_zt[b];
    for (int j = 0; j < NTOT; j++) {
        float zj1 = (j < NTOT - 1) ? g_zt[(j + 1) * BN + b] : 0.f;
        float tdist = (j < NTOT - 1) ? (zj1 - zj) : 1e10f;
        float4 rd = g_rgbd_f[j * BN + b];
        float dd = rd.w * tdist * dn;
        float alpha = 1.0f - expf(-dd);
        float wj = alpha * expf(-T);
        T += dd;
        c0 += wj * rd.x; c1 += wj * rd.y; c2 += wj * rd.z;
        acc += wj;
        depth += wj * zj;
        s1 += wj * g_zt[j * BN];
        zj = zj1;
    }
    c0 += bkgd[0] * (1.0f - acc);
    c1 += bkgd[1] * (1.0f - acc);
    c2 += bkgd[2] * (1.0f - acc);

    float o0x = origins[0], o0y = origins[1], o0z = origins[2];
    float d0x = dirs[0],    d0y = dirs[1],    d0z = dirs[2];
    float* po = out + (size_t)b * 16;
    po[8]  = c0; po[9] = c1; po[10] = c2;
    po[11] = depth; po[12] = acc;
    po[13] = acc * o0x + s1 * d0x;
    po[14] = acc * o0y + s1 * d0y;
    po[15] = acc * o0z + s1 * d0z;
}

// ---------------- launch ----------------
extern "C" void kernel_launch(void* const* d_in, const int* in_sizes, int n_in,
                              void* d_out, int out_size)
{
    const float* origins = (const float*)d_in[0];
    const float* dirs    = (const float*)d_in[1];
    const float* nearp   = (const float*)d_in[2];
    const float* farp    = (const float*)d_in[3];
    const float* bkgd    = (const float*)d_in[4];
    const float* w1_c = (const float*)d_in[5];
    const float* b1_c = (const float*)d_in[6];
    const float* w2_c = (const float*)d_in[7];
    const float* b2_c = (const float*)d_in[8];
    const float* wr_c = (const float*)d_in[9];
    const float* br_c = (const float*)d_in[10];
    const float* wd_c = (const float*)d_in[11];
    const float* bd_c = (const float*)d_in[12];
    const float* w1_f = (const float*)d_in[13];
    const float* b1_f = (const float*)d_in[14];
    const float* w2_f = (const float*)d_in[15];
    const float* b2_f = (const float*)d_in[16];
    const float* wr_f = (const float*)d_in[17];
    const float* br_f = (const float*)d_in[18];
    const float* wd_f = (const float*)d_in[19];
    const float* bd_f = (const float*)d_in[20];
    float* out = (float*)d_out;

    float4* rgbd_c;
    float4* rgbd_f;
    cudaGetSymbolAddress((void**)&rgbd_c, g_rgbd_c);
    cudaGetSymbolAddress((void**)&rgbd_f, g_rgbd_f);

    // 1) coarse MLP: 64*BN points, 64 per block
    mlp_pair_kernel<<<NCS * BN / PT, MT>>>(origins, dirs, nearp, farp,
                                           w1_c, b1_c, w2_c, b2_c, wr_c, br_c, wd_c, bd_c,
                                           0, rgbd_c);
    // 2) coarse render + PDF sample + stream merge (verified)
    render_coarse_kernel<<<BN / 128, 128>>>(origins, dirs, nearp, farp, bkgd, out);
    // 3) fine MLP: 192*BN points
    mlp_pair_kernel<<<NTOT * BN / PT, MT>>>(origins, dirs, nearp, farp,
                                            w1_f, b1_f, w2_f, b2_f, wr_f, br_f, wd_f, bd_f,
                                            1, rgbd_f);
    // 4) fine render (verified)
    render_fine_kernel<<<BN / 128, 128>>>(origins, dirs, bkgd, out);
}

// round 11
// speedup vs baseline: 1.5676x; 1.5676x over previous
#include <cuda_runtime.h>
#include <math.h>

#define BN 16384
#define NCS 64
#define NFS 128
#define NTOT 192
#define H 64
#define MT 256

typedef unsigned long long u64;

// ---------------- scratch ----------------
__device__ float4 g_rgbd_c[BN * NCS];
__device__ float4 g_rgbd_f[BN * NTOT];
__device__ float  g_zt[NTOT * BN];       // fine z_vals transposed: z[j*BN + b]

__device__ __forceinline__ float tval_of(float nb, float fb, int i) {
    float tt = (float)i * (1.0f / 63.0f);
    return nb * (1.0f - tt) + fb * tt;
}

// ---- f32x2 packed helpers ----
__device__ __forceinline__ u64 pk2(float lo, float hi) {
    u64 r; asm("mov.b64 %0, {%1, %2};" : "=l"(r) : "f"(lo), "f"(hi)); return r;
}
__device__ __forceinline__ void upk2(u64 v, float& lo, float& hi) {
    asm("mov.b64 {%0, %1}, %2;" : "=f"(lo), "=f"(hi) : "l"(v));
}
__device__ __forceinline__ u64 ffma2(u64 a, u64 b, u64 c) {
    u64 d; asm("fma.rn.f32x2 %0, %1, %2, %3;" : "=l"(d) : "l"(a), "l"(b), "l"(c)); return d;
}
__device__ __forceinline__ u64 relu2(u64 v) {
    float a, b; upk2(v, a, b);
    return pk2(fmaxf(a, 0.0f), fmaxf(b, 0.0f));
}

// ------------- MLP: one thread per point, k-dimension packed in f32x2 -------------
// hp[kk] = (h[2kk], h[2kk+1]) -> 32 u64 (64 regs) instead of mlp2's 128.
// Layer-2 unit jj: acc += hp[kk] * (w2[2kk][jj], w2[2kk+1][jj]); final = lo+hi+b2.
// All SMEM reads warp-uniform (broadcast). One sync (after staging) only.
__global__ __launch_bounds__(MT) void mlp_col_kernel(
    const float* __restrict__ origins, const float* __restrict__ dirs,
    const float* __restrict__ nearp,   const float* __restrict__ farp,
    const float* __restrict__ w1, const float* __restrict__ b1,
    const float* __restrict__ w2, const float* __restrict__ b2,
    const float* __restrict__ wr, const float* __restrict__ br,
    const float* __restrict__ wd, const float* __restrict__ bd,
    int use_z, float4* __restrict__ out_rgbd)
{
    __shared__ __align__(16) u64 s_w2p[H][34];   // [jj][kk]=(w2[2kk][jj],w2[2kk+1][jj]); pad->16B align kept
    __shared__ __align__(16) u64 s_w1p[4][32];   // packed-k rows: x,y,z,b1
    __shared__ __align__(16) u64 s_hdp[32][4];   // [jjp][c]=(head[2jjp][c],head[2jjp+1][c]); c3=wd
    __shared__ float s_b2[H];
    __shared__ float s_hb[4];

    int tid = threadIdx.x;

    // ---- stage (coalesced LDG: consecutive tid -> consecutive jj) ----
    for (int i = tid; i < H * 32; i += MT) {
        int jj = i & 63, kk = i >> 6;
        s_w2p[jj][kk] = pk2(w2[(2 * kk) * H + jj], w2[(2 * kk + 1) * H + jj]);
    }
    if (tid < 32) {
        s_w1p[0][tid] = pk2(w1[2 * tid],         w1[2 * tid + 1]);
        s_w1p[1][tid] = pk2(w1[H + 2 * tid],     w1[H + 2 * tid + 1]);
        s_w1p[2][tid] = pk2(w1[2 * H + 2 * tid], w1[2 * H + 2 * tid + 1]);
        s_w1p[3][tid] = pk2(b1[2 * tid],         b1[2 * tid + 1]);
    }
    if (tid < 128) {
        int jjp = tid >> 2, c = tid & 3;
        float v0 = (c < 3) ? wr[(2 * jjp) * 3 + c]     : wd[2 * jjp];
        float v1 = (c < 3) ? wr[(2 * jjp + 1) * 3 + c] : wd[2 * jjp + 1];
        s_hdp[jjp][c] = pk2(v0, v1);
    }
    if (tid < H) s_b2[tid] = b2[tid];
    if (tid < 3) s_hb[tid] = br[tid];
    if (tid == 3) s_hb[3] = bd[0];
    __syncthreads();

    unsigned p = blockIdx.x * MT + tid;   // grid sized exactly npoints/MT
    int b = (int)(p & (BN - 1));
    int j = (int)(p >> 14);

    float t = use_z ? g_zt[p] : tval_of(nearp[b], farp[b], j);
    float x = origins[3 * b]     + t * dirs[3 * b];
    float y = origins[3 * b + 1] + t * dirs[3 * b + 1];
    float z = origins[3 * b + 2] + t * dirs[3 * b + 2];
    u64 xp = pk2(x, x), yp = pk2(y, y), zp = pk2(z, z);

    // ---- layer 1 (packed-k), all in registers ----
    u64 hp[32];
    #pragma unroll
    for (int kk = 0; kk < 32; kk++) {
        u64 v = ffma2(xp, s_w1p[0][kk], s_w1p[3][kk]);
        v = ffma2(yp, s_w1p[1][kk], v);
        v = ffma2(zp, s_w1p[2][kk], v);
        hp[kk] = relu2(v);
    }

    // ---- layer 2 + head, 4 jj-chains per group, head packed over jj parity ----
    u64 hr0 = 0, hr1 = 0, hr2 = 0, hr3 = 0;
    #pragma unroll 1
    for (int jg = 0; jg < 16; jg++) {
        int jj0 = 4 * jg;
        u64 a0 = 0, a1 = 0, a2 = 0, a3 = 0;
        #pragma unroll
        for (int kk = 0; kk < 32; kk += 2) {
            ulonglong2 q0 = *reinterpret_cast<const ulonglong2*>(&s_w2p[jj0][kk]);
            ulonglong2 q1 = *reinterpret_cast<const ulonglong2*>(&s_w2p[jj0 + 1][kk]);
            ulonglong2 q2 = *reinterpret_cast<const ulonglong2*>(&s_w2p[jj0 + 2][kk]);
            ulonglong2 q3 = *reinterpret_cast<const ulonglong2*>(&s_w2p[jj0 + 3][kk]);
            a0 = ffma2(hp[kk], q0.x, a0);
            a1 = ffma2(hp[kk], q1.x, a1);
            a2 = ffma2(hp[kk], q2.x, a2);
            a3 = ffma2(hp[kk], q3.x, a3);
            a0 = ffma2(hp[kk + 1], q0.y, a0);
            a1 = ffma2(hp[kk + 1], q1.y, a1);
            a2 = ffma2(hp[kk + 1], q2.y, a2);
            a3 = ffma2(hp[kk + 1], q3.y, a3);
        }
        float l0, h0, l1, h1v, l2, h2, l3, h3;
        upk2(a0, l0, h0); upk2(a1, l1, h1v); upk2(a2, l2, h2); upk2(a3, l3, h3);
        float s0 = fmaxf(l0 + h0 + s_b2[jj0], 0.f);
        float s1 = fmaxf(l1 + h1v + s_b2[jj0 + 1], 0.f);
        float s2 = fmaxf(l2 + h2 + s_b2[jj0 + 2], 0.f);
        float s3 = fmaxf(l3 + h3 + s_b2[jj0 + 3], 0.f);
        u64 ap01 = pk2(s0, s1), ap23 = pk2(s2, s3);
        ulonglong2 dA0 = *reinterpret_cast<const ulonglong2*>(&s_hdp[2 * jg][0]);
        ulonglong2 dA1 = *reinterpret_cast<const ulonglong2*>(&s_hdp[2 * jg][2]);
        ulonglong2 dB0 = *reinterpret_cast<const ulonglong2*>(&s_hdp[2 * jg + 1][0]);
        ulonglong2 dB1 = *reinterpret_cast<const ulonglong2*>(&s_hdp[2 * jg + 1][2]);
        hr0 = ffma2(ap01, dA0.x, hr0); hr0 = ffma2(ap23, dB0.x, hr0);
        hr1 = ffma2(ap01, dA0.y, hr1); hr1 = ffma2(ap23, dB0.y, hr1);
        hr2 = ffma2(ap01, dA1.x, hr2); hr2 = ffma2(ap23, dB1.x, hr2);
        hr3 = ffma2(ap01, dA1.y, hr3); hr3 = ffma2(ap23, dB1.y, hr3);
    }

    float l, h;
    float4 o;
    upk2(hr0, l, h); o.x = 1.f / (1.f + expf(-(l + h + s_hb[0])));
    upk2(hr1, l, h); o.y = 1.f / (1.f + expf(-(l + h + s_hb[1])));
    upk2(hr2, l, h); o.z = 1.f / (1.f + expf(-(l + h + s_hb[2])));
    upk2(hr3, l, h); o.w = fmaxf(l + h + s_hb[3], 0.f);
    out_rgbd[p] = o;
}

// ---------------- coarse render + inverse-CDF + merge : one thread per ray (verified) ----------------
__global__ __launch_bounds__(128) void render_coarse_kernel(
    const float* __restrict__ origins, const float* __restrict__ dirs,
    const float* __restrict__ nearp,   const float* __restrict__ farp,
    const float* __restrict__ bkgd,
    float* __restrict__ out)
{
    int b = blockIdx.x * blockDim.x + threadIdx.x;
    if (b >= BN) return;

    float nb = nearp[b], fb = farp[b];
    float n0 = nearp[0], f0 = farp[0];
    float dx = dirs[3 * b], dy = dirs[3 * b + 1], dz = dirs[3 * b + 2];
    float dn = sqrtf(dx * dx + dy * dy + dz * dz);

    float w[NCS];
    float T = 0.f, c0 = 0.f, c1 = 0.f, c2 = 0.f, acc = 0.f, depth = 0.f, s0 = 0.f;
    for (int j = 0; j < NCS; j++) {
        float tj  = tval_of(nb, fb, j);
        float tdist = (j < NCS - 1) ? (tval_of(nb, fb, j + 1) - tj) : 1e10f;
        float4 rd = g_rgbd_c[j * BN + b];
        float dd = rd.w * tdist * dn;
        float alpha = 1.0f - expf(-dd);
        float trans = expf(-T);
        float wj = alpha * trans;
        T += dd;
        w[j] = wj;
        c0 += wj * rd.x; c1 += wj * rd.y; c2 += wj * rd.z;
        acc += wj;
        depth += wj * tj;
        s0 += wj * tval_of(n0, f0, j);
    }
    c0 += bkgd[0] * (1.0f - acc);
    c1 += bkgd[1] * (1.0f - acc);
    c2 += bkgd[2] * (1.0f - acc);

    float o0x = origins[0], o0y = origins[1], o0z = origins[2];
    float d0x = dirs[0],    d0y = dirs[1],    d0z = dirs[2];
    float* po = out + (size_t)b * 16;
    po[0] = c0; po[1] = c1; po[2] = c2;
    po[3] = depth; po[4] = acc;
    po[5] = acc * o0x + s0 * d0x;
    po[6] = acc * o0y + s0 * d0y;
    po[7] = acc * o0z + s0 * d0z;

    // ---- piecewise-constant PDF inverse-CDF sampling ----
    float ws = 0.f;
    for (int i = 0; i < 62; i++) ws += w[i + 1];
    float pad  = fmaxf(1e-5f - ws, 0.f);
    float padd = pad * (1.0f / 62.0f);
    ws += pad;
    float inv_ws = 1.0f / ws;

    float cdf[63];
    cdf[0] = 0.f;
    float run = 0.f;
    for (int i = 1; i <= 61; i++) {
        run += (w[i] + padd) * inv_ws;
        cdf[i] = fminf(run, 1.f);
    }
    cdf[62] = 1.f;

    const float F32EPS = 1.1920928955078125e-7f;
    const float ustep = (1.0f - F32EPS) * (1.0f / 127.0f);
    int i0 = 0;
    int ti = 0;
    int outn = 0;
    for (int s = 0; s < NFS; s++) {
        float u = (float)s * ustep;
        while (i0 + 1 < 62 + 1 && cdf[i0 + 1] <= u) i0++;
        float cg0 = cdf[i0], cg1 = cdf[i0 + 1];
        float bg0 = 0.5f * (tval_of(nb, fb, i0)     + tval_of(nb, fb, i0 + 1));
        float bg1 = 0.5f * (tval_of(nb, fb, i0 + 1) + tval_of(nb, fb, i0 + 2));
        float denom = cg1 - cg0;
        float tf = (denom > 0.f) ? (u - cg0) / denom : 0.f;
        tf = fminf(fmaxf(tf, 0.f), 1.f);
        float zs = bg0 + tf * (bg1 - bg0);
        while (ti < NCS && tval_of(nb, fb, ti) <= zs) {
            g_zt[outn * BN + b] = tval_of(nb, fb, ti);
            outn++; ti++;
        }
        g_zt[outn * BN + b] = zs;
        outn++;
    }
    while (ti < NCS) {
        g_zt[outn * BN + b] = tval_of(nb, fb, ti);
        outn++; ti++;
    }
}

// ---------------- fine render : one thread per ray (verified) ----------------
__global__ __launch_bounds__(128) void render_fine_kernel(
    const float* __restrict__ origins, const float* __restrict__ dirs,
    const float* __restrict__ bkgd,
    float* __restrict__ out)
{
    int b = blockIdx.x * blockDim.x + threadIdx.x;
    if (b >= BN) return;

    float dx = dirs[3 * b], dy = dirs[3 * b + 1], dz = dirs[3 * b + 2];
    float dn = sqrtf(dx * dx + dy * dy + dz * dz);

    float T = 0.f, c0 = 0.f, c1 = 0.f, c2 = 0.f, acc = 0.f, depth = 0.f, s1 = 0.f;
    float zj = g_zt[b];
    for (int j = 0; j < NTOT; j++) {
        float zj1 = (j < NTOT - 1) ? g_zt[(j + 1) * BN + b] : 0.f;
        float tdist = (j < NTOT - 1) ? (zj1 - zj) : 1e10f;
        float4 rd = g_rgbd_f[j * BN + b];
        float dd = rd.w * tdist * dn;
        float alpha = 1.0f - expf(-dd);
        float wj = alpha * expf(-T);
        T += dd;
        c0 += wj * rd.x; c1 += wj * rd.y; c2 += wj * rd.z;
        acc += wj;
        depth += wj * zj;
        s1 += wj * g_zt[j * BN];
        zj = zj1;
    }
    c0 += bkgd[0] * (1.0f - acc);
    c1 += bkgd[1] * (1.0f - acc);
    c2 += bkgd[2] * (1.0f - acc);

    float o0x = origins[0], o0y = origins[1], o0z = origins[2];
    float d0x = dirs[0],    d0y = dirs[1],    d0z = dirs[2];
    float* po = out + (size_t)b * 16;
    po[8]  = c0; po[9] = c1; po[10] = c2;
    po[11] = depth; po[12] = acc;
    po[13] = acc * o0x + s1 * d0x;
    po[14] = acc * o0y + s1 * d0y;
    po[15] = acc * o0z + s1 * d0z;
}

// ---------------- launch ----------------
extern "C" void kernel_launch(void* const* d_in, const int* in_sizes, int n_in,
                              void* d_out, int out_size)
{
    const float* origins = (const float*)d_in[0];
    const float* dirs    = (const float*)d_in[1];
    const float* nearp   = (const float*)d_in[2];
    const float* farp    = (const float*)d_in[3];
    const float* bkgd    = (const float*)d_in[4];
    const float* w1_c = (const float*)d_in[5];
    const float* b1_c = (const float*)d_in[6];
    const float* w2_c = (const float*)d_in[7];
    const float* b2_c = (const float*)d_in[8];
    const float* wr_c = (const float*)d_in[9];
    const float* br_c = (const float*)d_in[10];
    const float* wd_c = (const float*)d_in[11];
    const float* bd_c = (const float*)d_in[12];
    const float* w1_f = (const float*)d_in[13];
    const float* b1_f = (const float*)d_in[14];
    const float* w2_f = (const float*)d_in[15];
    const float* b2_f = (const float*)d_in[16];
    const float* wr_f = (const float*)d_in[17];
    const float* br_f = (const float*)d_in[18];
    const float* wd_f = (const float*)d_in[19];
    const float* bd_f = (const float*)d_in[20];
    float* out = (float*)d_out;

    float4* rgbd_c;
    float4* rgbd_f;
    cudaGetSymbolAddress((void**)&rgbd_c, g_rgbd_c);
    cudaGetSymbolAddress((void**)&rgbd_f, g_rgbd_f);

    // 1) coarse MLP: 64*BN points, one per thread
    mlp_col_kernel<<<NCS * BN / MT, MT>>>(origins, dirs, nearp, farp,
                                          w1_c, b1_c, w2_c, b2_c, wr_c, br_c, wd_c, bd_c,
                                          0, rgbd_c);
    // 2) coarse render + PDF sample + stream merge (verified)
    render_coarse_kernel<<<BN / 128, 128>>>(origins, dirs, nearp, farp, bkgd, out);
    // 3) fine MLP: 192*BN points
    mlp_col_kernel<<<NTOT * BN / MT, MT>>>(origins, dirs, nearp, farp,
                                           w1_f, b1_f, w2_f, b2_f, wr_f, br_f, wd_f, bd_f,
                                           1, rgbd_f);
    // 4) fine render (verified)
    render_fine_kernel<<<BN / 128, 128>>>(origins, dirs, bkgd, out);
}